// round 11
// baseline (speedup 1.0000x reference)
#include <cuda_runtime.h>
#include <math.h>

#define NUM_TASKS 1000
#define NF 256
#define NH 128
#define BATCH 4096
#define CHUNK 8
#define GRID_PERSIST 444   // 148 SMs x 3 CTAs/SM (regs=80 -> 3 CTAs)

// Scratch (no allocations allowed)
__device__ int g_off[NUM_TASKS + 1];
__device__ int g_order[BATCH];
__device__ int g_task_ctr;

// ---------------------------------------------------------------------------
// Fused prep: count + scan + scatter + work-queue reset, ONE single-block kernel.
// ---------------------------------------------------------------------------
__global__ __launch_bounds__(1024) void prep_k(const int* __restrict__ task_ids, int n) {
    __shared__ int cnt[NUM_TASKS];
    __shared__ int sc[1024];
    int tid = threadIdx.x;

    if (tid == 0) g_task_ctr = 0;          // reset persistent-queue counter

    for (int i = tid; i < NUM_TASKS; i += 1024) cnt[i] = 0;
    __syncthreads();
    for (int i = tid; i < n; i += 1024) atomicAdd(&cnt[task_ids[i]], 1);
    __syncthreads();

    sc[tid] = (tid < NUM_TASKS) ? cnt[tid] : 0;
    __syncthreads();
    for (int d = 1; d < 1024; d <<= 1) {
        int v = (tid >= d) ? sc[tid - d] : 0;
        __syncthreads();
        sc[tid] += v;
        __syncthreads();
    }
    if (tid < NUM_TASKS) {
        g_off[tid + 1] = sc[tid];
        if (tid == 0) g_off[0] = 0;
        cnt[tid] = (tid == 0) ? 0 : sc[tid - 1];
    }
    __syncthreads();

    for (int i = tid; i < n; i += 1024) {
        int p = atomicAdd(&cnt[task_ids[i]], 1);
        g_order[p] = i;
    }
}

__device__ __forceinline__ float gelu_exact(float h) {
    return 0.5f * h * (1.0f + erff(h * 0.70710678118654752f));
}

// ---------------------------------------------------------------------------
// Chunk body. 256 threads = 8 warp-groups (wg = tid>>5), each wg streams 32
// contiguous W rows; lane owns hidden cols 4*lane..4*lane+3 via LDG.128.
// 8 partial-h fragments combined in smem, layer-2 on first 128 threads.
// Pad slots (s >= S) replicate sample 0; computed but never stored.
// ---------------------------------------------------------------------------
template<int SS>
__device__ __forceinline__ void do_chunk(
    int base, int S, int tid, int wg, int lane, int j,
    const float* __restrict__ x, const float* __restrict__ W,
    float b1, float w2, float b2,
    float (*sx)[NF], float (*hpart)[CHUNK][NH], int* sidx, float (*sred)[CHUNK],
    float* __restrict__ out)
{
    #pragma unroll
    for (int s = 0; s < SS; s++) {
        int src = base + ((s < S) ? s : 0);
        int ord = __ldg(&g_order[src]);
        if (tid == s) sidx[s] = ord;
        sx[s][tid] = x[(size_t)ord * NF + tid];
    }
    __syncthreads();

    int f0 = wg * 32;
    const float4* __restrict__ Wv =
        (const float4*)(W + (size_t)f0 * NH) + lane;   // row stride = 32 float4

    float4 acc[SS];
    #pragma unroll
    for (int s = 0; s < SS; s++) acc[s] = make_float4(0.f, 0.f, 0.f, 0.f);

    #pragma unroll 8
    for (int r = 0; r < 32; r++) {
        float4 wv = Wv[r * 32];             // LDG.128
        const float* sxf = &sx[0][f0 + r];
        #pragma unroll
        for (int s = 0; s < SS; s++) {
            float xs = sxf[s * NF];         // smem broadcast
            acc[s].x += xs * wv.x;
            acc[s].y += xs * wv.y;
            acc[s].z += xs * wv.z;
            acc[s].w += xs * wv.w;
        }
    }

    #pragma unroll
    for (int s = 0; s < SS; s++)
        *(float4*)&hpart[wg][s][lane * 4] = acc[s];
    __syncthreads();

    if (tid < NH) {
        int l2lane = tid & 31, l2wid = tid >> 5;
        #pragma unroll
        for (int s = 0; s < SS; s++) {
            float h = b1;
            #pragma unroll
            for (int g = 0; g < 8; g++) h += hpart[g][s][j];
            float v = gelu_exact(h) * w2;
            v += __shfl_xor_sync(0xffffffff, v, 16);
            v += __shfl_xor_sync(0xffffffff, v, 8);
            v += __shfl_xor_sync(0xffffffff, v, 4);
            v += __shfl_xor_sync(0xffffffff, v, 2);
            v += __shfl_xor_sync(0xffffffff, v, 1);
            if (l2lane == 0) sred[l2wid][s] = v;
        }
    }
    __syncthreads();

    if (tid < S) {
        float sum = sred[0][tid] + sred[1][tid] + sred[2][tid] + sred[3][tid];
        out[sidx[tid]] = sum + b2;
    }
    __syncthreads();
}

// Persistent CTAs: grid = 444 (one full wave), tasks pulled from atomic queue.
__global__ __launch_bounds__(256, 3) void mlp_k(
    const float* __restrict__ x,
    const float* __restrict__ l1_emb,
    const float* __restrict__ l1_bias,
    const float* __restrict__ l2_emb,
    const float* __restrict__ l2_bias,
    float* __restrict__ out)
{
    int tid  = threadIdx.x;
    int wg   = tid >> 5;
    int lane = tid & 31;
    int j    = tid & 127;

    __shared__ float sx[CHUNK][NF];           // 8 KB
    __shared__ float hpart[8][CHUNK][NH];     // 32 KB
    __shared__ int   sidx[CHUNK];
    __shared__ float sred[4][CHUNK];
    __shared__ int   s_task;

    for (;;) {
        if (tid == 0) s_task = atomicAdd(&g_task_ctr, 1);
        __syncthreads();
        int t = s_task;
        if (t >= NUM_TASKS) break;

        int beg = g_off[t];
        int n   = g_off[t + 1] - beg;
        if (n == 0) { __syncthreads(); continue; }

        const float* __restrict__ W = l1_emb + (size_t)t * (NF * NH);
        float b1 = l1_bias[t * NH + j];
        float w2 = l2_emb[t * NH + j];
        float b2 = l2_bias[t];

        int pos = beg, rem = n;
        while (rem > 0) {
            if (rem > 4) {
                do_chunk<8>(pos, min(rem, 8), tid, wg, lane, j, x, W, b1, w2, b2,
                            sx, hpart, sidx, sred, out);
                pos += 8; rem -= 8;
            } else if (rem > 2) {
                do_chunk<4>(pos, rem, tid, wg, lane, j, x, W, b1, w2, b2,
                            sx, hpart, sidx, sred, out);
                rem = 0;
            } else {
                do_chunk<2>(pos, rem, tid, wg, lane, j, x, W, b1, w2, b2,
                            sx, hpart, sidx, sred, out);
                rem = 0;
            }
        }
        __syncthreads();   // all threads done with smem before next task fetch
    }
}

extern "C" void kernel_launch(void* const* d_in, const int* in_sizes, int n_in,
                              void* d_out, int out_size) {
    const float* x       = (const float*)d_in[0];
    const int*   task_id = (const int*)  d_in[1];
    const float* l1_emb  = (const float*)d_in[2];
    const float* l1_bias = (const float*)d_in[3];
    const float* l2_emb  = (const float*)d_in[4];
    const float* l2_bias = (const float*)d_in[5];
    float* out = (float*)d_out;

    int nb = in_sizes[1];  // BATCH

    prep_k<<<1, 1024>>>(task_id, nb);
    mlp_k<<<GRID_PERSIST, 256>>>(x, l1_emb, l1_bias, l2_emb, l2_bias, out);
}